// round 2
// baseline (speedup 1.0000x reference)
#include <cuda_runtime.h>

namespace {

constexpr int BATCH = 16;
constexpr int DIM   = 48;
constexpr int HID   = 16;
constexpr int CC    = 8;          // gated half
constexpr int Hh    = 256;
constexpr int Ww    = 256;
constexpr int HW    = Hh * Ww;
constexpr int TH    = 32;
constexpr int TW    = 32;
constexpr int PTH   = TH + 2;
constexpr int PTW   = TW + 2;
constexpr int NPAD  = PTH * PTW;  // 1156
constexpr int NINT  = TH * TW;    // 1024
constexpr int THREADS = 256;
constexpr float LN_EPS = 1e-5f;

__device__ __forceinline__ float gelu_f(float v) {
    // exact GELU: 0.5*v*(1+erf(v/sqrt(2)))
    return 0.5f * v * (1.0f + erff(v * 0.70710678118654752440f));
}

__global__ __launch_bounds__(THREADS)
void fused_block(const float* __restrict__ x,
                 const float* __restrict__ gW1, const float* __restrict__ gb1,
                 const float* __restrict__ ggamma, const float* __restrict__ gbeta,
                 const float* __restrict__ gdww, const float* __restrict__ gdwb,
                 const float* __restrict__ gpww, const float* __restrict__ gpwb,
                 const float* __restrict__ gW2, const float* __restrict__ gb2,
                 float* __restrict__ out)
{
    __shared__ __align__(16) float sW1[DIM * HID];   // [d][j]
    __shared__ __align__(16) float sW2[CC * DIM];    // [c][d]
    __shared__ __align__(16) float sb2[DIM];
    __shared__ float sb1[HID];
    __shared__ float sPw[CC * CC];                   // [cout][cin]
    __shared__ float sPwb[CC];
    __shared__ float sDw[CC * 9];                    // [c][ky*3+kx]
    __shared__ float sDwb[CC];
    __shared__ float sG[CC];
    __shared__ float sBt[CC];

    extern __shared__ float dyn[];
    float* sN  = dyn;                 // CC planes of NPAD (layernormed x2, halo'd)
    float* sX1 = dyn + CC * NPAD;     // CC planes of NINT (gate input)

    const int tid = threadIdx.x;
    for (int i = tid; i < DIM * HID; i += THREADS) sW1[i] = gW1[i];
    for (int i = tid; i < CC * DIM;  i += THREADS) sW2[i] = gW2[i];
    if (tid < CC * 9) sDw[tid] = gdww[tid];
    if (tid < HID)    sb1[tid] = gb1[tid];
    if (tid < DIM)    sb2[tid] = gb2[tid];
    if (tid < CC * CC) sPw[tid] = gpww[tid];
    if (tid < CC) {
        sPwb[tid] = gpwb[tid];
        sDwb[tid] = gdwb[tid];
        sG[tid]   = ggamma[tid];
        sBt[tid]  = gbeta[tid];
    }

    const int b  = blockIdx.z;
    const int h0 = blockIdx.y * TH;
    const int w0 = blockIdx.x * TW;
    const float* xb = x + (size_t)b * DIM * HW;     // batch base (tokens: 48 contiguous floats)

    __syncthreads();

    // ---------------- Phase 1: front (GEMM 48->16, double GELU, split, LN) ----------------
    #pragma unroll 1
    for (int p = tid; p < NPAD; p += THREADS) {
        const int py = p / PTW;
        const int px = p - py * PTW;
        const int gh = h0 + py - 1;
        const int gw = w0 + px - 1;

        if ((unsigned)gh >= (unsigned)Hh || (unsigned)gw >= (unsigned)Ww) {
            // zero-padding for 'SAME' conv
            #pragma unroll
            for (int c = 0; c < CC; ++c) sN[c * NPAD + p] = 0.0f;
            continue;
        }

        float y[HID];
        #pragma unroll
        for (int j = 0; j < HID; ++j) y[j] = sb1[j];

        // token = 48 contiguous floats (reshape, not transpose!)
        const float4* xp = (const float4*)(xb + (size_t)(gh * Ww + gw) * DIM);
        #pragma unroll
        for (int d4 = 0; d4 < DIM / 4; ++d4) {
            const float4 xv = __ldg(xp + d4);
            const float xs[4] = {xv.x, xv.y, xv.z, xv.w};
            #pragma unroll
            for (int k = 0; k < 4; ++k) {
                const int d = d4 * 4 + k;
                const float4* w4 = (const float4*)(sW1 + d * HID);
                const float4 a0 = w4[0], a1 = w4[1], a2 = w4[2], a3 = w4[3];
                const float xvk = xs[k];
                y[0]  = fmaf(xvk, a0.x, y[0]);   y[1]  = fmaf(xvk, a0.y, y[1]);
                y[2]  = fmaf(xvk, a0.z, y[2]);   y[3]  = fmaf(xvk, a0.w, y[3]);
                y[4]  = fmaf(xvk, a1.x, y[4]);   y[5]  = fmaf(xvk, a1.y, y[5]);
                y[6]  = fmaf(xvk, a1.z, y[6]);   y[7]  = fmaf(xvk, a1.w, y[7]);
                y[8]  = fmaf(xvk, a2.x, y[8]);   y[9]  = fmaf(xvk, a2.y, y[9]);
                y[10] = fmaf(xvk, a2.z, y[10]);  y[11] = fmaf(xvk, a2.w, y[11]);
                y[12] = fmaf(xvk, a3.x, y[12]);  y[13] = fmaf(xvk, a3.y, y[13]);
                y[14] = fmaf(xvk, a3.z, y[14]);  y[15] = fmaf(xvk, a3.w, y[15]);
            }
        }

        #pragma unroll
        for (int j = 0; j < HID; ++j) y[j] = gelu_f(gelu_f(y[j]));

        // LayerNorm over y[8..15]
        float m = 0.0f;
        #pragma unroll
        for (int c = 0; c < CC; ++c) m += y[CC + c];
        m *= 0.125f;
        float var = 0.0f;
        #pragma unroll
        for (int c = 0; c < CC; ++c) { const float dd = y[CC + c] - m; var = fmaf(dd, dd, var); }
        const float inv = rsqrtf(var * 0.125f + LN_EPS);

        #pragma unroll
        for (int c = 0; c < CC; ++c)
            sN[c * NPAD + p] = (y[CC + c] - m) * inv * sG[c] + sBt[c];

        if (py >= 1 && py <= TH && px >= 1 && px <= TW) {
            const int q = (py - 1) * TW + (px - 1);
            #pragma unroll
            for (int c = 0; c < CC; ++c) sX1[c * NINT + q] = y[c];
        }
    }

    __syncthreads();

    // ---------------- Phase 2: dw 3x3 + pw 1x1 + gate + GEMM 8->48 ----------------
    float* ob = out + (size_t)b * DIM * HW;
    #pragma unroll 1
    for (int q = tid; q < NINT; q += THREADS) {
        const int ty = q >> 5;
        const int tx = q & 31;
        const int py = ty + 1;
        const int px = tx + 1;

        float ncen[CC];
        #pragma unroll
        for (int c = 0; c < CC; ++c) ncen[c] = sN[c * NPAD + py * PTW + px];

        float g[CC];
        #pragma unroll
        for (int c = 0; c < CC; ++c) {
            const float* nb = sN + c * NPAD;
            const float* k9 = sDw + c * 9;
            float acc = sDwb[c];
            #pragma unroll
            for (int dy = 0; dy < 3; ++dy) {
                const float* r = nb + (py - 1 + dy) * PTW + (px - 1);
                acc = fmaf(r[0], k9[dy * 3 + 0], acc);
                acc = fmaf(r[1], k9[dy * 3 + 1], acc);
                acc = fmaf(r[2], k9[dy * 3 + 2], acc);
            }
            float chv = sPwb[c];
            #pragma unroll
            for (int cin = 0; cin < CC; ++cin)
                chv = fmaf(ncen[cin], sPw[c * CC + cin], chv);
            g[c] = sX1[c * NINT + q] * acc * chv;
        }

        // out[d] = sum_c g[c]*W2[c][d] + b2[d]; NCHW scatter (coalesced per d across warp)
        float* op = ob + (h0 + ty) * Ww + (w0 + tx);
        #pragma unroll
        for (int d4 = 0; d4 < DIM / 4; ++d4) {
            float4 acc = *(const float4*)(sb2 + d4 * 4);
            #pragma unroll
            for (int c = 0; c < CC; ++c) {
                const float4 wv = *(const float4*)(sW2 + c * DIM + d4 * 4);
                const float gc = g[c];
                acc.x = fmaf(gc, wv.x, acc.x);
                acc.y = fmaf(gc, wv.y, acc.y);
                acc.z = fmaf(gc, wv.z, acc.z);
                acc.w = fmaf(gc, wv.w, acc.w);
            }
            op[(size_t)(d4 * 4 + 0) * HW] = acc.x;
            op[(size_t)(d4 * 4 + 1) * HW] = acc.y;
            op[(size_t)(d4 * 4 + 2) * HW] = acc.z;
            op[(size_t)(d4 * 4 + 3) * HW] = acc.w;
        }
    }
}

} // namespace

extern "C" void kernel_launch(void* const* d_in, const int* in_sizes, int n_in,
                              void* d_out, int out_size) {
    const float* x     = (const float*)d_in[0];
    const float* W1    = (const float*)d_in[1];
    const float* b1    = (const float*)d_in[2];
    const float* gamma = (const float*)d_in[3];
    const float* beta  = (const float*)d_in[4];
    const float* dw_w  = (const float*)d_in[5];
    const float* dw_b  = (const float*)d_in[6];
    const float* pw_w  = (const float*)d_in[7];
    const float* pw_b  = (const float*)d_in[8];
    const float* W2    = (const float*)d_in[9];
    const float* b2    = (const float*)d_in[10];
    float* out = (float*)d_out;

    const int shmem = (CC * NPAD + CC * NINT) * (int)sizeof(float); // 69760 B
    cudaFuncSetAttribute(fused_block, cudaFuncAttributeMaxDynamicSharedMemorySize, shmem);

    dim3 grid(Ww / TW, Hh / TH, BATCH);
    fused_block<<<grid, THREADS, shmem>>>(x, W1, b1, gamma, beta,
                                          dw_w, dw_b, pw_w, pw_b, W2, b2, out);
}